// round 1
// baseline (speedup 1.0000x reference)
#include <cuda_runtime.h>

// EfficientGCN preprocess on GB300.
// x: (N=128, C=3, T=300, V=25, M=2) fp32, conn: int32[25]
// out: (N, 3, 2C=6, T, V, M) fp32
//
// One thread per (n, t, v); M=2 handled as float2 (m is innermost dim).
// float2-linearized input index:  ((n*3 + c)*300 + t)*25 + v
// float2-linearized output index: ((n*18 + b*6 + c2)*300 + t)*25 + v
// Every output element is written exactly once -> no zeroing pass needed.

#define N_ 128
#define C_ 3
#define T_ 300
#define V_ 25

__global__ __launch_bounds__(256) void egcn_preprocess_kernel(
    const float2* __restrict__ x2,
    const int* __restrict__ conn,
    float2* __restrict__ out2)
{
    const int P = N_ * T_ * V_;   // 960000
    int p = blockIdx.x * blockDim.x + threadIdx.x;
    if (p >= P) return;

    int v  = p % V_;
    int nt = p / V_;
    int t  = nt % T_;
    int n  = nt / T_;

    const int cstride = T_ * V_;          // 7500 float2 per channel
    const int base    = n * (C_ * cstride) + t * V_;   // channel 0, this (t, row)

    int pv = __ldg(&conn[v]);             // parent joint

    float2 a[3], cen[3], par[3], d1[3], d2[3];

    const bool has_vel = (t < T_ - 2);

#pragma unroll
    for (int c = 0; c < C_; ++c) {
        const float2* row = x2 + base + c * cstride;
        float2 av = row[v];
        a[c]   = av;
        cen[c] = row[1];       // center joint, broadcast across warp
        par[c] = row[pv];
        if (has_vel) {
            float2 n1 = row[V_ + v];       // t+1
            float2 n2 = row[2 * V_ + v];   // t+2
            d1[c] = make_float2(n1.x - av.x, n1.y - av.y);
            d2[c] = make_float2(n2.x - av.x, n2.y - av.y);
        } else {
            d1[c] = make_float2(0.f, 0.f);
            d2[c] = make_float2(0.f, 0.f);
        }
    }

    // bone vectors + angles
    float2 bv[3];
#pragma unroll
    for (int c = 0; c < C_; ++c)
        bv[c] = make_float2(a[c].x - par[c].x, a[c].y - par[c].y);

    float lx = sqrtf(bv[0].x * bv[0].x + bv[1].x * bv[1].x + bv[2].x * bv[2].x) + 1e-4f;
    float ly = sqrtf(bv[0].y * bv[0].y + bv[1].y * bv[1].y + bv[2].y * bv[2].y) + 1e-4f;
    float rlx = 1.0f / lx;
    float rly = 1.0f / ly;

    float2 ang[3];
#pragma unroll
    for (int c = 0; c < C_; ++c) {
        ang[c].x = acosf(bv[c].x * rlx);
        ang[c].y = acosf(bv[c].y * rly);
    }

    // output: base index for (n, b, c2) block
    const int ostride = T_ * V_;                        // 7500 float2 per (b,c2)
    const int obase   = n * 18 * ostride + t * V_ + v;  // b=0,c2=0

#pragma unroll
    for (int c = 0; c < C_; ++c) {
        // branch 0: joint = [x ; x - x_center]
        out2[obase + (0 * 6 + c    ) * ostride] = a[c];
        out2[obase + (0 * 6 + c + 3) * ostride] =
            make_float2(a[c].x - cen[c].x, a[c].y - cen[c].y);
        // branch 1: velocity = [v1 ; v2]
        out2[obase + (1 * 6 + c    ) * ostride] = d1[c];
        out2[obase + (1 * 6 + c + 3) * ostride] = d2[c];
        // branch 2: bone = [bone_vec ; bone_angle]
        out2[obase + (2 * 6 + c    ) * ostride] = bv[c];
        out2[obase + (2 * 6 + c + 3) * ostride] = ang[c];
    }
}

extern "C" void kernel_launch(void* const* d_in, const int* in_sizes, int n_in,
                              void* d_out, int out_size)
{
    const float2* x2  = (const float2*)d_in[0];
    const int* conn   = (const int*)d_in[1];
    float2* out2      = (float2*)d_out;

    const int P = N_ * T_ * V_;          // 960000
    const int threads = 256;
    const int blocks = (P + threads - 1) / threads;
    egcn_preprocess_kernel<<<blocks, threads>>>(x2, conn, out2);
}